// round 1
// baseline (speedup 1.0000x reference)
#include <cuda_runtime.h>
#include <math.h>

// Problem dims (fixed by the dataset)
#define N_TOK 8192
#define D_IN  1024
#define D_QK  128
#define D_V   1024
#define D_W1  1280   // concat rows: Wq(128) | Wk(128) | Wv(1024)
#define CAP   1024   // per-row candidate capacity before dense fallback
#define LOG_THR 25.0f // exp(-25) ~ 1.4e-11 ; dropped mass <= 8192*e^-25 ~ 1.1e-7

// ---------------- scratch (static device globals; no allocs) ----------------
static __device__ float  g_W1 [D_W1 * D_IN];                 // 5 MB
static __device__ float  g_qkv[(size_t)N_TOK * D_W1];        // 40 MB (q|k|v per row)
static __device__ float  g_S  [(size_t)N_TOK * N_TOK];       // 256 MB raw scaled scores
static __device__ float  g_m  [N_TOK];
static __device__ float  g_l  [N_TOK];
static __device__ int    g_cnt[N_TOK];
static __device__ float2 g_cand[(size_t)N_TOK * CAP];        // (.x = j bits, .y = exp(s-m)) 64 MB
static __device__ float  g_sa [(size_t)N_TOK * D_V];         // 32 MB
static __device__ float  g_h  [(size_t)N_TOK * D_V];         // 32 MB
static __device__ float  g_tmp[(size_t)N_TOK * D_V];         // 32 MB

// ---------------- weight concat: g_W1 = [Wq; Wk; Wv] ----------------
__global__ void concat_w(const float* __restrict__ Wq,
                         const float* __restrict__ Wk,
                         const float* __restrict__ Wv)
{
    int i = blockIdx.x * blockDim.x + threadIdx.x;
    const int total = D_W1 * D_IN;
    for (; i < total; i += gridDim.x * blockDim.x) {
        int r = i / D_IN, c = i - r * D_IN;
        float v;
        if (r < 128)      v = Wq[r * D_IN + c];
        else if (r < 256) v = Wk[(r - 128) * D_IN + c];
        else              v = Wv[(r - 256) * D_IN + c];
        g_W1[i] = v;
    }
}

// ---------------- fp32 SIMT GEMM: C[M,N] = alpha * A[M,K] * B[N,K]^T ----------------
// Block tile 128x128, K-tile 8, 256 threads, 8x8 microtile.
// mode 0: A=x(ext),   B=g_W1,       C=g_qkv   (qkv projection)
// mode 1: A=q(g_qkv), B=k(g_qkv+128),C=g_S    (scores, alpha=sqrt(128))
// mode 2: A=g_h,      B=Wl(ext),    C=g_tmp   (output projection)
__global__ __launch_bounds__(256, 2)
void sgemm_nt(int mode, const float* __restrict__ Aext, const float* __restrict__ Bext,
              int K, int lda, int ldb, int ldc, float alpha)
{
    const float* A; const float* B; float* C;
    if (mode == 0)      { A = Aext;  B = g_W1;        C = g_qkv; }
    else if (mode == 1) { A = g_qkv; B = g_qkv + 128; C = g_S;   }
    else                { A = g_h;   B = Bext;        C = g_tmp; }

    __shared__ float As[8][128];
    __shared__ float Bs[8][128];

    const int tid  = threadIdx.x;
    const int m0   = blockIdx.y * 128;
    const int n0   = blockIdx.x * 128;
    const int lrow = tid >> 1;          // 0..127
    const int lcol = (tid & 1) << 2;    // 0 or 4
    const int tx   = tid & 15;          // n-dir
    const int ty   = tid >> 4;          // m-dir

    const float* Ap = A + (size_t)(m0 + lrow) * lda + lcol;
    const float* Bp = B + (size_t)(n0 + lrow) * ldb + lcol;

    float acc[8][8];
#pragma unroll
    for (int i = 0; i < 8; i++)
#pragma unroll
        for (int j = 0; j < 8; j++) acc[i][j] = 0.0f;

    for (int k0 = 0; k0 < K; k0 += 8) {
        float4 av = *(const float4*)(Ap + k0);
        float4 bv = *(const float4*)(Bp + k0);
        __syncthreads();
        As[lcol + 0][lrow] = av.x; As[lcol + 1][lrow] = av.y;
        As[lcol + 2][lrow] = av.z; As[lcol + 3][lrow] = av.w;
        Bs[lcol + 0][lrow] = bv.x; Bs[lcol + 1][lrow] = bv.y;
        Bs[lcol + 2][lrow] = bv.z; Bs[lcol + 3][lrow] = bv.w;
        __syncthreads();
#pragma unroll
        for (int kk = 0; kk < 8; kk++) {
            float4 a0 = *(const float4*)&As[kk][ty * 8];
            float4 a1 = *(const float4*)&As[kk][ty * 8 + 4];
            float4 b0 = *(const float4*)&Bs[kk][tx * 8];
            float4 b1 = *(const float4*)&Bs[kk][tx * 8 + 4];
            float ar[8] = {a0.x, a0.y, a0.z, a0.w, a1.x, a1.y, a1.z, a1.w};
            float br[8] = {b0.x, b0.y, b0.z, b0.w, b1.x, b1.y, b1.z, b1.w};
#pragma unroll
            for (int i = 0; i < 8; i++)
#pragma unroll
                for (int j = 0; j < 8; j++)
                    acc[i][j] += ar[i] * br[j];
        }
    }

#pragma unroll
    for (int i = 0; i < 8; i++) {
        float* Cp = C + (size_t)(m0 + ty * 8 + i) * ldc + (n0 + tx * 8);
        float4 o0 = make_float4(alpha * acc[i][0], alpha * acc[i][1],
                                alpha * acc[i][2], alpha * acc[i][3]);
        float4 o1 = make_float4(alpha * acc[i][4], alpha * acc[i][5],
                                alpha * acc[i][6], alpha * acc[i][7]);
        *(float4*)(Cp)     = o0;
        *(float4*)(Cp + 4) = o1;
    }
}

// ---------------- per-row softmax stats + deterministic candidate compaction ----------------
__global__ __launch_bounds__(256)
void softmax_stats()
{
    const int r   = blockIdx.x;
    const int tid = threadIdx.x;
    const float* Srow = g_S + (size_t)r * N_TOK;

    __shared__ float red[256];
    __shared__ int   sc[256];
    __shared__ int   s_over;
    if (tid == 0) s_over = 0;

    // pass 1: row max
    float lmax = -1e30f;
    for (int j = tid; j < N_TOK; j += 256) lmax = fmaxf(lmax, Srow[j]);
    red[tid] = lmax;
    __syncthreads();
    for (int s = 128; s > 0; s >>= 1) {
        if (tid < s) red[tid] = fmaxf(red[tid], red[tid + s]);
        __syncthreads();
    }
    const float m = red[0];
    __syncthreads();

    // pass 2: sum of exp + local candidate collection (ascending j per thread)
    const float thr = m - LOG_THR;
    float lsum = 0.0f;
    int   lj[8]; float lw[8];
    int   lc = 0; int over = 0;
    for (int j = tid; j < N_TOK; j += 256) {
        float s = Srow[j];
        float w = __expf(s - m);
        lsum += w;
        if (s > thr) {
            if (lc < 8) { lj[lc] = j; lw[lc] = w; }
            else over = 1;
            lc++;
        }
    }
    if (over) atomicOr(&s_over, 1);
    red[tid] = lsum;
    __syncthreads();
    for (int s = 128; s > 0; s >>= 1) {
        if (tid < s) red[tid] += red[tid + s];
        __syncthreads();
    }
    const float l = red[0];

    // exclusive scan of per-thread counts (deterministic compaction order)
    sc[tid] = lc;
    __syncthreads();
    for (int off = 1; off < 256; off <<= 1) {
        int t = (tid >= off) ? sc[tid - off] : 0;
        __syncthreads();
        sc[tid] += t;
        __syncthreads();
    }
    const int total = sc[255];
    const int myoff = sc[tid] - lc;
    const int dense = (total > CAP) || (s_over != 0);

    if (!dense) {
        const int n = (lc < 8) ? lc : 8;
        for (int i = 0; i < n; i++)
            g_cand[(size_t)r * CAP + myoff + i] =
                make_float2(__int_as_float(lj[i]), lw[i]);
    }
    if (tid == 0) {
        g_m[r]   = m;
        g_l[r]   = l;
        g_cnt[r] = dense ? (CAP + 1) : total;
    }
}

// ---------------- sparse attn@v: sa[r,:] = sum_cand (p/l) * v[j,:] ----------------
__global__ __launch_bounds__(64)
void attn_av()
{
    const int r   = blockIdx.x;
    const int tid = threadIdx.x;
    const int cnt = g_cnt[r];
    const float invl = 1.0f / g_l[r];
    const int d = tid * 16;
    const float* vbase = g_qkv + 256;   // v region, row stride D_W1

    float4 a0 = make_float4(0, 0, 0, 0), a1 = a0, a2 = a0, a3 = a0;

    if (cnt <= CAP) {
        const float2* cl = g_cand + (size_t)r * CAP;
        for (int i = 0; i < cnt; i++) {
            float2 c = cl[i];
            int   j = __float_as_int(c.x);
            float w = c.y * invl;
            const float* vr = vbase + (size_t)j * D_W1 + d;
            float4 v0 = *(const float4*)(vr);
            float4 v1 = *(const float4*)(vr + 4);
            float4 v2 = *(const float4*)(vr + 8);
            float4 v3 = *(const float4*)(vr + 12);
            a0.x += w * v0.x; a0.y += w * v0.y; a0.z += w * v0.z; a0.w += w * v0.w;
            a1.x += w * v1.x; a1.y += w * v1.y; a1.z += w * v1.z; a1.w += w * v1.w;
            a2.x += w * v2.x; a2.y += w * v2.y; a2.z += w * v2.z; a2.w += w * v2.w;
            a3.x += w * v3.x; a3.y += w * v3.y; a3.z += w * v3.z; a3.w += w * v3.w;
        }
    } else {
        // dense fallback (deterministic, rarely/never taken)
        const float m = g_m[r];
        const float* Srow = g_S + (size_t)r * N_TOK;
        for (int j = 0; j < N_TOK; j++) {
            float w = __expf(Srow[j] - m) * invl;
            if (w > 1e-12f) {
                const float* vr = vbase + (size_t)j * D_W1 + d;
                float4 v0 = *(const float4*)(vr);
                float4 v1 = *(const float4*)(vr + 4);
                float4 v2 = *(const float4*)(vr + 8);
                float4 v3 = *(const float4*)(vr + 12);
                a0.x += w * v0.x; a0.y += w * v0.y; a0.z += w * v0.z; a0.w += w * v0.w;
                a1.x += w * v1.x; a1.y += w * v1.y; a1.z += w * v1.z; a1.w += w * v1.w;
                a2.x += w * v2.x; a2.y += w * v2.y; a2.z += w * v2.z; a2.w += w * v2.w;
                a3.x += w * v3.x; a3.y += w * v3.y; a3.z += w * v3.z; a3.w += w * v3.w;
            }
        }
    }

    float* out = g_sa + (size_t)r * D_V + d;
    *(float4*)(out)      = a0;
    *(float4*)(out + 4)  = a1;
    *(float4*)(out + 8)  = a2;
    *(float4*)(out + 12) = a3;
}

// ---------------- fused residual + LayerNorm (elementwise_affine=False) ----------------
// mode 0: out = g_h    = LN(x_ext + g_sa)
// mode 1: out = out_ext= LN(g_sa  + g_tmp)
__global__ __launch_bounds__(256)
void ln_fuse(int mode, const float* __restrict__ ext_a, float* __restrict__ ext_out)
{
    const int r   = blockIdx.x;
    const int tid = threadIdx.x;
    const float* a; const float* b; float* o;
    if (mode == 0) { a = ext_a; b = g_sa;  o = g_h; }
    else           { a = g_sa;  b = g_tmp; o = ext_out; }

    const float4 av = *(const float4*)(a + (size_t)r * D_V + tid * 4);
    const float4 bv = *(const float4*)(b + (size_t)r * D_V + tid * 4);
    float4 y = make_float4(av.x + bv.x, av.y + bv.y, av.z + bv.z, av.w + bv.w);

    float s  = y.x + y.y + y.z + y.w;
    float sq = y.x * y.x + y.y * y.y + y.z * y.z + y.w * y.w;

    __shared__ float2 red2[256];
    red2[tid] = make_float2(s, sq);
    __syncthreads();
    for (int st = 128; st > 0; st >>= 1) {
        if (tid < st) {
            red2[tid].x += red2[tid + st].x;
            red2[tid].y += red2[tid + st].y;
        }
        __syncthreads();
    }
    const float mean = red2[0].x * (1.0f / (float)D_V);
    const float var  = red2[0].y * (1.0f / (float)D_V) - mean * mean;
    const float rstd = rsqrtf(var + 1e-5f);

    float4 outv = make_float4((y.x - mean) * rstd, (y.y - mean) * rstd,
                              (y.z - mean) * rstd, (y.w - mean) * rstd);
    *(float4*)(o + (size_t)r * D_V + tid * 4) = outv;
}

// ---------------- launch sequence ----------------
extern "C" void kernel_launch(void* const* d_in, const int* in_sizes, int n_in,
                              void* d_out, int out_size)
{
    const float* x  = (const float*)d_in[0];
    const float* Wq = (const float*)d_in[1];
    const float* Wk = (const float*)d_in[2];
    const float* Wv = (const float*)d_in[3];
    const float* Wl = (const float*)d_in[4];
    float* out = (float*)d_out;

    const float scale = 11.313708498984760f; // sqrt(128)

    // 1) concat weights
    concat_w<<<256, 256>>>(Wq, Wk, Wv);

    // 2) qkv = x @ W1^T   (M=8192, N=1280, K=1024)
    sgemm_nt<<<dim3(D_W1 / 128, N_TOK / 128), 256>>>(0, x, nullptr,
                                                     D_IN, D_IN, D_IN, D_W1, 1.0f);

    // 3) S = scale * q @ k^T  (M=N=8192, K=128)
    sgemm_nt<<<dim3(N_TOK / 128, N_TOK / 128), 256>>>(1, nullptr, nullptr,
                                                      D_QK, D_W1, D_W1, N_TOK, scale);

    // 4) per-row max / sumexp / candidate list
    softmax_stats<<<N_TOK, 256>>>();

    // 5) sa = softmax(S) @ v  (sparse gather, dense fallback)
    attn_av<<<N_TOK, 64>>>();

    // 6) h = LN(x + sa)
    ln_fuse<<<N_TOK, 256>>>(0, x, nullptr);

    // 7) tmp = h @ Wl^T  (M=8192, N=1024, K=1024)
    sgemm_nt<<<dim3(D_V / 128, N_TOK / 128), 256>>>(2, nullptr, Wl,
                                                    D_IN, D_IN, D_IN, D_V, 1.0f);

    // 8) out = LN(sa + tmp)
    ln_fuse<<<N_TOK, 256>>>(1, nullptr, out);
}

// round 3
// speedup vs baseline: 2.4528x; 2.4528x over previous
#include <cuda_runtime.h>
#include <cuda_bf16.h>
#include <cstdint>
#include <math.h>

// Problem dims (fixed by the dataset)
#define N_TOK 8192
#define D_IN  1024
#define D_QK  128
#define D_V   1024
#define D_W1  1280   // concat rows: Wq(128) | Wk(128) | Wv(1024)
#define CAP   1024
#define LOG_THR 25.0f

// ---------------- scratch (static device globals; no allocs) ----------------
static __device__ __align__(16) __nv_bfloat16 g_xh [(size_t)N_TOK * D_IN];
static __device__ __align__(16) __nv_bfloat16 g_xl [(size_t)N_TOK * D_IN];
static __device__ __align__(16) __nv_bfloat16 g_W1h[(size_t)D_W1 * D_IN];
static __device__ __align__(16) __nv_bfloat16 g_W1l[(size_t)D_W1 * D_IN];
static __device__ __align__(16) __nv_bfloat16 g_Wlh[(size_t)D_V * D_IN];
static __device__ __align__(16) __nv_bfloat16 g_Wll[(size_t)D_V * D_IN];
static __device__ __align__(16) __nv_bfloat16 g_qkh[(size_t)N_TOK * 256];  // q:0..127 | k:128..255
static __device__ __align__(16) __nv_bfloat16 g_qkl[(size_t)N_TOK * 256];
static __device__ __align__(16) __nv_bfloat16 g_hh [(size_t)N_TOK * D_IN];
static __device__ __align__(16) __nv_bfloat16 g_hl [(size_t)N_TOK * D_IN];
static __device__ float  g_v  [(size_t)N_TOK * D_V];
static __device__ float  g_S  [(size_t)N_TOK * N_TOK];        // 256 MB
static __device__ float  g_m  [N_TOK];
static __device__ float  g_l  [N_TOK];
static __device__ int    g_cnt[N_TOK];
static __device__ float2 g_cand[(size_t)N_TOK * CAP];
static __device__ float  g_sa [(size_t)N_TOK * D_V];
static __device__ float  g_tmp[(size_t)N_TOK * D_V];

// ---------------- helpers ----------------
__device__ __forceinline__ uint32_t smem_u32(const void* p) {
    uint32_t a;
    asm("{ .reg .u64 t; cvta.to.shared.u64 t, %1; cvt.u32.u64 %0, t; }" : "=r"(a) : "l"(p));
    return a;
}
__device__ __forceinline__ void split_bf16(float v, __nv_bfloat16& h, __nv_bfloat16& l) {
    h = __float2bfloat16(v);
    l = __float2bfloat16(v - __bfloat162float(h));
}
__device__ __forceinline__ void atomicMaxFloat(float* addr, float v) {
    if (v >= 0.0f) atomicMax((int*)addr, __float_as_int(v));
    else           atomicMin((unsigned int*)addr, __float_as_uint(v));
}

#define LDSM_X4(r, addr)                                                        \
    asm volatile("ldmatrix.sync.aligned.m8n8.x4.shared.b16 {%0,%1,%2,%3}, [%4];" \
        : "=r"((r)[0]), "=r"((r)[1]), "=r"((r)[2]), "=r"((r)[3]) : "r"(addr))

#define MMA_BF16(c, a, b)                                                       \
    asm volatile("mma.sync.aligned.m16n8k16.row.col.f32.bf16.bf16.f32 "         \
        "{%0,%1,%2,%3}, {%4,%5,%6,%7}, {%8,%9}, {%0,%1,%2,%3};"                 \
        : "+f"((c)[0]), "+f"((c)[1]), "+f"((c)[2]), "+f"((c)[3])                \
        : "r"((a)[0]), "r"((a)[1]), "r"((a)[2]), "r"((a)[3]),                   \
          "r"((b)[0]), "r"((b)[1]))

#define CP_ASYNC16(dst, src) \
    asm volatile("cp.async.cg.shared.global [%0], [%1], 16;" :: "r"(dst), "l"(src))
#define CP_COMMIT()  asm volatile("cp.async.commit_group;")
#define CP_WAIT(n)   asm volatile("cp.async.wait_group %0;" :: "n"(n))

// ---------------- weight / input prep: bf16 hi-lo split ----------------
__global__ void prep_weights(const float* __restrict__ Wq, const float* __restrict__ Wk,
                             const float* __restrict__ Wv, const float* __restrict__ Wl)
{
    const int stride = gridDim.x * blockDim.x;
    int g = blockIdx.x * blockDim.x + threadIdx.x;
    for (int i = g; i < D_W1 * D_IN; i += stride) {
        int r = i >> 10, c = i & 1023;
        float v;
        if (r < 128)      v = Wq[r * D_IN + c];
        else if (r < 256) v = Wk[(r - 128) * D_IN + c];
        else              v = Wv[(r - 256) * D_IN + c];
        split_bf16(v, g_W1h[i], g_W1l[i]);
    }
    for (int i = g; i < D_V * D_IN; i += stride)
        split_bf16(Wl[i], g_Wlh[i], g_Wll[i]);
}

__global__ void split_x(const float* __restrict__ x)
{
    const int stride = gridDim.x * blockDim.x;
    int g = blockIdx.x * blockDim.x + threadIdx.x;
    for (int i = g; i < N_TOK * D_IN; i += stride)
        split_bf16(x[i], g_xh[i], g_xl[i]);
    for (int i = g; i < N_TOK; i += stride)
        g_m[i] = -1e30f;
}

// ---------------- bf16x3 tensor-core GEMM: C = alpha * A @ B^T ----------------
// CTA tile 128x128, K-chunk 64, 8 warps (warp tile 32x64), 2-stage cp.async.
// mode 0: A=xh/xl,  B=W1h/W1l (K=1024) -> qk bf16 split + v fp32
// mode 1: A=qh/ql,  B=kh/kl   (K=128)  -> g_S fp32 (alpha=sqrt128) + rowmax atomics
// mode 2: A=hh/hl,  B=Wlh/Wll (K=1024) -> g_tmp fp32
#define TILE_B   16384          // one 128x64 bf16 tile (swizzled)
#define STAGE_B  (4 * TILE_B)   // Ah, Al, Bh, Bl
#define SMEM_BYTES (2 * STAGE_B)

__global__ __launch_bounds__(256, 1)
void gemm_mma(int mode)
{
    extern __shared__ char smem[];
    const uint32_t sb  = smem_u32(smem);
    const int tid  = threadIdx.x;
    const int wid  = tid >> 5;
    const int lane = tid & 31;
    const int m0 = blockIdx.y * 128;
    const int n0 = blockIdx.x * 128;

    const __nv_bfloat16 *Ah, *Al, *Bh, *Bl;
    int lda, ldb, K;
    if (mode == 0)      { Ah = g_xh;  Al = g_xl;  Bh = g_W1h;       Bl = g_W1l;       lda = 1024; ldb = 1024; K = 1024; }
    else if (mode == 1) { Ah = g_qkh; Al = g_qkl; Bh = g_qkh + 128; Bl = g_qkl + 128; lda = 256;  ldb = 256;  K = 128;  }
    else                { Ah = g_hh;  Al = g_hl;  Bh = g_Wlh;       Bl = g_Wll;       lda = 1024; ldb = 1024; K = 1024; }

    const __nv_bfloat16* bases[4] = {
        Ah + (size_t)m0 * lda, Al + (size_t)m0 * lda,
        Bh + (size_t)n0 * ldb, Bl + (size_t)n0 * ldb };
    const int lds[4] = { lda, lda, ldb, ldb };

    // async fill of one stage (4 tiles of 128 rows x 64 bf16, SW128 swizzle)
    auto load_stage = [&](int st, int k0) {
#pragma unroll
        for (int it = 0; it < 16; it++) {
            int idx  = tid + it * 256;
            int tile = idx >> 10;
            int r    = (idx >> 3) & 127;
            int g    = idx & 7;
            const __nv_bfloat16* src = bases[tile] + (size_t)r * lds[tile] + k0 + g * 8;
            uint32_t off = (uint32_t)(r * 128 + g * 16);
            off ^= (off >> 3) & 0x70;
            CP_ASYNC16(sb + st * STAGE_B + tile * TILE_B + off, src);
        }
        CP_COMMIT();
    };

    const int wm = (wid & 3) * 32;   // warp M offset in tile
    const int wn = (wid >> 2) * 64;  // warp N offset in tile

    float acc[2][8][4];
#pragma unroll
    for (int i = 0; i < 2; i++)
#pragma unroll
        for (int j = 0; j < 8; j++)
#pragma unroll
            for (int k = 0; k < 4; k++) acc[i][j][k] = 0.0f;

    auto compute_stage = [&](int st) {
        const uint32_t base = sb + st * STAGE_B;
#pragma unroll
        for (int k16 = 0; k16 < 4; k16++) {
            uint32_t ah[2][4], al[2][4];
#pragma unroll
            for (int mi = 0; mi < 2; mi++) {
                int row = wm + mi * 16 + (lane & 15);
                int c16 = k16 * 2 + (lane >> 4);
                uint32_t off = (uint32_t)(row * 128 + c16 * 16);
                off ^= (off >> 3) & 0x70;
                LDSM_X4(ah[mi], base + 0 * TILE_B + off);
                LDSM_X4(al[mi], base + 1 * TILE_B + off);
            }
            uint32_t bh[4][4], bl[4][4];
#pragma unroll
            for (int nj = 0; nj < 4; nj++) {
                int row = wn + nj * 16 + (lane & 7) + ((lane >> 4) << 3);
                int c16 = k16 * 2 + ((lane >> 3) & 1);
                uint32_t off = (uint32_t)(row * 128 + c16 * 16);
                off ^= (off >> 3) & 0x70;
                LDSM_X4(bh[nj], base + 2 * TILE_B + off);
                LDSM_X4(bl[nj], base + 3 * TILE_B + off);
            }
#pragma unroll
            for (int mi = 0; mi < 2; mi++)
#pragma unroll
                for (int nj = 0; nj < 4; nj++) {
                    MMA_BF16(acc[mi][nj * 2],     ah[mi], (bh[nj] + 0));
                    MMA_BF16(acc[mi][nj * 2],     ah[mi], (bl[nj] + 0));
                    MMA_BF16(acc[mi][nj * 2],     al[mi], (bh[nj] + 0));
                    MMA_BF16(acc[mi][nj * 2 + 1], ah[mi], (bh[nj] + 2));
                    MMA_BF16(acc[mi][nj * 2 + 1], ah[mi], (bl[nj] + 2));
                    MMA_BF16(acc[mi][nj * 2 + 1], al[mi], (bh[nj] + 2));
                }
        }
    };

    const int nch = K / 64;
    load_stage(0, 0);
    for (int ch = 0; ch < nch; ch++) {
        if (ch + 1 < nch) { load_stage((ch + 1) & 1, (ch + 1) * 64); CP_WAIT(1); }
        else              { CP_WAIT(0); }
        __syncthreads();
        compute_stage(ch & 1);
        __syncthreads();
    }

    // ---------------- epilogue ----------------
    // c-frag: c0,c1 -> (row = l>>2,      col = 2(l&3), +1)
    //         c2,c3 -> (row = l>>2 + 8,  same cols)
    const int qr = lane >> 2;
    const int qc = (lane & 3) * 2;

    if (mode == 1) {
        const float alpha = 11.313708498984760f; // sqrt(128)
        float rmax0[2] = { -1e30f, -1e30f };     // per mi: row l>>2
        float rmax1[2] = { -1e30f, -1e30f };     // per mi: row l>>2 + 8
#pragma unroll
        for (int mi = 0; mi < 2; mi++) {
            const int r0 = m0 + wm + mi * 16 + qr;
#pragma unroll
            for (int ni = 0; ni < 8; ni++) {
                const int col = n0 + wn + ni * 8 + qc;
                float c0 = alpha * acc[mi][ni][0], c1 = alpha * acc[mi][ni][1];
                float c2 = alpha * acc[mi][ni][2], c3 = alpha * acc[mi][ni][3];
                rmax0[mi] = fmaxf(rmax0[mi], fmaxf(c0, c1));
                rmax1[mi] = fmaxf(rmax1[mi], fmaxf(c2, c3));
                *(float2*)(g_S + (size_t)r0 * N_TOK + col)       = make_float2(c0, c1);
                *(float2*)(g_S + (size_t)(r0 + 8) * N_TOK + col) = make_float2(c2, c3);
            }
        }
        // reduce across the 4 lanes sharing each row, then one atomic per row
#pragma unroll
        for (int mi = 0; mi < 2; mi++) {
#pragma unroll
            for (int s = 1; s < 4; s <<= 1) {
                rmax0[mi] = fmaxf(rmax0[mi], __shfl_xor_sync(0xFFFFFFFF, rmax0[mi], s));
                rmax1[mi] = fmaxf(rmax1[mi], __shfl_xor_sync(0xFFFFFFFF, rmax1[mi], s));
            }
            if ((lane & 3) == 0) {
                const int r0 = m0 + wm + mi * 16 + qr;
                atomicMaxFloat(&g_m[r0],     rmax0[mi]);
                atomicMaxFloat(&g_m[r0 + 8], rmax1[mi]);
            }
        }
    } else if (mode == 0) {
#pragma unroll
        for (int mi = 0; mi < 2; mi++) {
            const int r0 = m0 + wm + mi * 16 + qr;
#pragma unroll
            for (int ni = 0; ni < 8; ni++) {
                const int col = n0 + wn + ni * 8 + qc;
                if (col < 256) {
                    __nv_bfloat16 h0, l0, h1, l1;
#pragma unroll
                    for (int half = 0; half < 2; half++) {
                        const int rr = r0 + half * 8;
                        split_bf16(acc[mi][ni][half * 2 + 0], h0, l0);
                        split_bf16(acc[mi][ni][half * 2 + 1], h1, l1);
                        *(__nv_bfloat162*)(g_qkh + (size_t)rr * 256 + col) =
                            __nv_bfloat162(h0, h1);
                        *(__nv_bfloat162*)(g_qkl + (size_t)rr * 256 + col) =
                            __nv_bfloat162(l0, l1);
                    }
                } else {
                    const int vc = col - 256;
                    *(float2*)(g_v + (size_t)r0 * D_V + vc) =
                        make_float2(acc[mi][ni][0], acc[mi][ni][1]);
                    *(float2*)(g_v + (size_t)(r0 + 8) * D_V + vc) =
                        make_float2(acc[mi][ni][2], acc[mi][ni][3]);
                }
            }
        }
    } else {
#pragma unroll
        for (int mi = 0; mi < 2; mi++) {
            const int r0 = m0 + wm + mi * 16 + qr;
#pragma unroll
            for (int ni = 0; ni < 8; ni++) {
                const int col = n0 + wn + ni * 8 + qc;
                *(float2*)(g_tmp + (size_t)r0 * D_V + col) =
                    make_float2(acc[mi][ni][0], acc[mi][ni][1]);
                *(float2*)(g_tmp + (size_t)(r0 + 8) * D_V + col) =
                    make_float2(acc[mi][ni][2], acc[mi][ni][3]);
            }
        }
    }
}

// ---------------- softmax: single pass (max precomputed in scores epilogue) ---
__global__ __launch_bounds__(256)
void softmax_stats()
{
    const int r   = blockIdx.x;
    const int tid = threadIdx.x;
    const float* Srow = g_S + (size_t)r * N_TOK;
    const float m = g_m[r];

    __shared__ float red[256];
    __shared__ int   sc[256];
    __shared__ int   s_over;
    if (tid == 0) s_over = 0;
    __syncthreads();

    const float thr = m - LOG_THR;
    float lsum = 0.0f;
    int   lj[8]; float lw[8];
    int   lc = 0; int over = 0;
    for (int j = tid; j < N_TOK; j += 256) {
        float s = Srow[j];
        float w = __expf(s - m);
        lsum += w;
        if (s > thr) {
            if (lc < 8) { lj[lc] = j; lw[lc] = w; }
            else over = 1;
            lc++;
        }
    }
    if (over) atomicOr(&s_over, 1);
    red[tid] = lsum;
    __syncthreads();
    for (int s = 128; s > 0; s >>= 1) {
        if (tid < s) red[tid] += red[tid + s];
        __syncthreads();
    }
    const float l = red[0];

    sc[tid] = lc;
    __syncthreads();
    for (int off = 1; off < 256; off <<= 1) {
        int t = (tid >= off) ? sc[tid - off] : 0;
        __syncthreads();
        sc[tid] += t;
        __syncthreads();
    }
    const int total = sc[255];
    const int myoff = sc[tid] - lc;
    const int dense = (total > CAP) || (s_over != 0);

    if (!dense) {
        const int n = (lc < 8) ? lc : 8;
        for (int i = 0; i < n; i++)
            g_cand[(size_t)r * CAP + myoff + i] =
                make_float2(__int_as_float(lj[i]), lw[i]);
    }
    if (tid == 0) {
        g_l[r]   = l;
        g_cnt[r] = dense ? (CAP + 1) : total;
    }
}

// ---------------- sparse attn@v ----------------
__global__ __launch_bounds__(64)
void attn_av()
{
    const int r   = blockIdx.x;
    const int tid = threadIdx.x;
    const int cnt = g_cnt[r];
    const float invl = 1.0f / g_l[r];
    const int d = tid * 16;

    float4 a0 = make_float4(0, 0, 0, 0), a1 = a0, a2 = a0, a3 = a0;

    if (cnt <= CAP) {
        const float2* cl = g_cand + (size_t)r * CAP;
        for (int i = 0; i < cnt; i++) {
            float2 c = cl[i];
            int   j = __float_as_int(c.x);
            float w = c.y * invl;
            const float* vr = g_v + (size_t)j * D_V + d;
            float4 v0 = *(const float4*)(vr);
            float4 v1 = *(const float4*)(vr + 4);
            float4 v2 = *(const float4*)(vr + 8);
            float4 v3 = *(const float4*)(vr + 12);
            a0.x += w * v0.x; a0.y += w * v0.y; a0.z += w * v0.z; a0.w += w * v0.w;
            a1.x += w * v1.x; a1.y += w * v1.y; a1.z += w * v1.z; a1.w += w * v1.w;
            a2.x += w * v2.x; a2.y += w * v2.y; a2.z += w * v2.z; a2.w += w * v2.w;
            a3.x += w * v3.x; a3.y += w * v3.y; a3.z += w * v3.z; a3.w += w * v3.w;
        }
    } else {
        const float m = g_m[r];
        const float* Srow = g_S + (size_t)r * N_TOK;
        for (int j = 0; j < N_TOK; j++) {
            float w = __expf(Srow[j] - m) * invl;
            if (w > 1e-12f) {
                const float* vr = g_v + (size_t)j * D_V + d;
                float4 v0 = *(const float4*)(vr);
                float4 v1 = *(const float4*)(vr + 4);
                float4 v2 = *(const float4*)(vr + 8);
                float4 v3 = *(const float4*)(vr + 12);
                a0.x += w * v0.x; a0.y += w * v0.y; a0.z += w * v0.z; a0.w += w * v0.w;
                a1.x += w * v1.x; a1.y += w * v1.y; a1.z += w * v1.z; a1.w += w * v1.w;
                a2.x += w * v2.x; a2.y += w * v2.y; a2.z += w * v2.z; a2.w += w * v2.w;
                a3.x += w * v3.x; a3.y += w * v3.y; a3.z += w * v3.z; a3.w += w * v3.w;
            }
        }
    }

    float* out = g_sa + (size_t)r * D_V + d;
    *(float4*)(out)      = a0;
    *(float4*)(out + 4)  = a1;
    *(float4*)(out + 8)  = a2;
    *(float4*)(out + 12) = a3;
}

// ---------------- fused residual + LayerNorm ----------------
// mode 0: h = LN(x + sa) -> bf16 split (g_hh/g_hl)
// mode 1: out = LN(sa + tmp) -> fp32 out
__global__ __launch_bounds__(256)
void ln_fuse(int mode, const float* __restrict__ ext_a, float* __restrict__ ext_out)
{
    const int r   = blockIdx.x;
    const int tid = threadIdx.x;
    const float* a; const float* b;
    if (mode == 0) { a = ext_a; b = g_sa; }
    else           { a = g_sa;  b = g_tmp; }

    const float4 av = *(const float4*)(a + (size_t)r * D_V + tid * 4);
    const float4 bv = *(const float4*)(b + (size_t)r * D_V + tid * 4);
    float4 y = make_float4(av.x + bv.x, av.y + bv.y, av.z + bv.z, av.w + bv.w);

    float s  = y.x + y.y + y.z + y.w;
    float sq = y.x * y.x + y.y * y.y + y.z * y.z + y.w * y.w;

    __shared__ float2 red2[256];
    red2[tid] = make_float2(s, sq);
    __syncthreads();
    for (int st = 128; st > 0; st >>= 1) {
        if (tid < st) {
            red2[tid].x += red2[tid + st].x;
            red2[tid].y += red2[tid + st].y;
        }
        __syncthreads();
    }
    const float mean = red2[0].x * (1.0f / (float)D_V);
    const float var  = red2[0].y * (1.0f / (float)D_V) - mean * mean;
    const float rstd = rsqrtf(var + 1e-5f);

    float o0 = (y.x - mean) * rstd, o1 = (y.y - mean) * rstd;
    float o2 = (y.z - mean) * rstd, o3 = (y.w - mean) * rstd;

    if (mode == 0) {
        size_t base = (size_t)r * D_V + tid * 4;
        split_bf16(o0, g_hh[base + 0], g_hl[base + 0]);
        split_bf16(o1, g_hh[base + 1], g_hl[base + 1]);
        split_bf16(o2, g_hh[base + 2], g_hl[base + 2]);
        split_bf16(o3, g_hh[base + 3], g_hl[base + 3]);
    } else {
        *(float4*)(ext_out + (size_t)r * D_V + tid * 4) = make_float4(o0, o1, o2, o3);
    }
}

// ---------------- launch sequence ----------------
extern "C" void kernel_launch(void* const* d_in, const int* in_sizes, int n_in,
                              void* d_out, int out_size)
{
    const float* x  = (const float*)d_in[0];
    const float* Wq = (const float*)d_in[1];
    const float* Wk = (const float*)d_in[2];
    const float* Wv = (const float*)d_in[3];
    const float* Wl = (const float*)d_in[4];
    float* out = (float*)d_out;

    cudaFuncSetAttribute(gemm_mma, cudaFuncAttributeMaxDynamicSharedMemorySize, SMEM_BYTES);

    prep_weights<<<256, 256>>>(Wq, Wk, Wv, Wl);
    split_x<<<512, 256>>>(x);

    // qkv = x @ W1^T  (M=8192, N=1280, K=1024) -> qk bf16 split + v fp32
    gemm_mma<<<dim3(D_W1 / 128, N_TOK / 128), 256, SMEM_BYTES>>>(0);

    // S = sqrt(128) * q @ k^T  (M=N=8192, K=128) + row-max atomics
    gemm_mma<<<dim3(N_TOK / 128, N_TOK / 128), 256, SMEM_BYTES>>>(1);

    softmax_stats<<<N_TOK, 256>>>();
    attn_av<<<N_TOK, 64>>>();
    ln_fuse<<<N_TOK, 256>>>(0, x, nullptr);

    // tmp = h @ Wl^T  (M=8192, N=1024, K=1024)
    gemm_mma<<<dim3(D_V / 128, N_TOK / 128), 256, SMEM_BYTES>>>(2);

    ln_fuse<<<N_TOK, 256>>>(1, nullptr, out);
}